// round 9
// baseline (speedup 1.0000x reference)
#include <cuda_runtime.h>
#include <cstdint>

#define BATCH 16
#define A_N   261888
#define NWRD  8184          // A_N/32 validity words per image
#define PRE   2000
#define MROWS 2048          // padded mask rows (rows >= PRE never written: stay 0)
#define POST  1000
#define SORTN 4096          // max sort size
#define NSEG  64            // chunks per image
#define SEGSZ 256           // candidate slots per chunk
#define NCAND (NSEG * SEGSZ)
#define NH    2048          // selection histogram buckets over [PREF, 1)
#define NW    32            // 32 x uint64 words cover 2048 bits
#define IMGF      1024.0f
#define NMS_THR_F 0.7f
#define MIN_SZ_F  16.0f
#define PREF      0.98f
#define HSCALE    102400.0f // NH / (1 - PREF)

typedef unsigned long long u64;

// ---------------- device scratch ----------------
__device__ unsigned g_valid[BATCH * NWRD];
__device__ int    g_ccnt[BATCH * NSEG];        // written unconditionally each launch
__device__ u64    g_cand[BATCH * NCAND];
__device__ float4 g_box[BATCH * PRE];
__device__ float  g_sc2[BATCH * PRE];
__device__ u64    g_mask[BATCH * MROWS * NW];  // lower-tri + padding rows: always 0

// ---------------- fast exp: FMA pipe only, ~5e-9 rel err ----------------
__device__ __forceinline__ float fast_exp(float x) {
    x = fmaxf(x, -80.0f);
    float z = fmaf(x, 1.4426950408889634f, 12582912.0f);
    float nf = z - 12582912.0f;
    int   ni = __float_as_int(z) - 0x4B400000;
    float t = fmaf(nf, -0.693145751953125f, x);
    t = fmaf(nf, -1.42860677e-6f, t);
    float p = 1.9841270e-4f;
    p = fmaf(p, t, 1.3888889e-3f);
    p = fmaf(p, t, 8.3333338e-3f);
    p = fmaf(p, t, 4.1666668e-2f);
    p = fmaf(p, t, 1.6666667e-1f);
    p = fmaf(p, t, 5.0e-1f);
    p = fmaf(p, t, 1.0f);
    p = fmaf(p, t, 1.0f);
    return p * __int_as_float((ni + 127) << 23);
}

__device__ __forceinline__ float4 decode_clip(const float4 a, const float4 d) {
    float aw = a.z - a.x;
    float ah = a.w - a.y;
    float ax = a.x + 0.5f * aw;
    float ay = a.y + 0.5f * ah;
    float dw = fminf(d.z, 4.0f);
    float dh = fminf(d.w, 4.0f);
    float px = d.x * aw + ax;
    float py = d.y * ah + ay;
    float pw = fast_exp(dw) * aw;
    float ph = fast_exp(dh) * ah;
    float x1 = fminf(fmaxf(px - 0.5f * pw, 0.0f), IMGF);
    float y1 = fminf(fmaxf(py - 0.5f * ph, 0.0f), IMGF);
    float x2 = fminf(fmaxf(px + 0.5f * pw, 0.0f), IMGF);
    float y2 = fminf(fmaxf(py + 0.5f * ph, 0.0f), IMGF);
    return make_float4(x1, y1, x2, y2);
}

// ---------------- kernel 1: decode + validity bitmap + prefilter collect --------
__global__ void k_decode(const float4* __restrict__ anchors,
                         const float4* __restrict__ deltas,
                         const float* __restrict__ scores) {
    __shared__ int s_cnt;
    const unsigned FULL = 0xffffffffu;
    int b = blockIdx.x >> 6;
    int chunk = blockIdx.x & 63;
    int start = chunk * 4096;
    int end = min(start + 4096, A_N);      // last chunk: 3840 (multiple of 32)
    int tid = threadIdx.x;
    if (tid == 0) s_cnt = 0;
    __syncthreads();
    int   li[8];
    float lv[8];
    int c = 0;
    for (int i = start + tid; i < end; i += blockDim.x) {
        float4 a = anchors[i];
        float4 d = deltas[(size_t)b * A_N + i];
        float  s = scores[(size_t)b * A_N + i];
        float4 bx = decode_clip(a, d);
        bool valid = (bx.z - bx.x >= MIN_SZ_F) && (bx.w - bx.y >= MIN_SZ_F);
        unsigned m = __ballot_sync(FULL, valid);
        if ((tid & 31) == 0) g_valid[b * NWRD + (i >> 5)] = m;
        if (valid && s >= PREF && c < 8) { li[c] = i; lv[c] = s; c++; }
    }
    int ofs = 0;
    if (c) ofs = atomicAdd(&s_cnt, c);     // shared atomic only
    for (int k = 0; k < c; k++) {
        int pos = ofs + k;
        if (pos < SEGSZ) {
            unsigned lo = ~(unsigned)li[k];            // lower index wins ties
            g_cand[(size_t)(b * NSEG + chunk) * SEGSZ + pos] =
                ((u64)__float_as_uint(lv[k]) << 32) | lo;
        }
    }
    __syncthreads();
    if (tid == 0) g_ccnt[b * NSEG + chunk] = s_cnt;    // raw count, every launch
}

// ---------------- kernel 2: select top-PRE + bitonic sort (desc) + gather -------
__device__ __forceinline__ void cex(u64& a, u64& b, bool desc) {
    bool sw = desc ? (a < b) : (a > b);
    if (sw) { u64 t = a; a = b; b = t; }
}

__device__ __forceinline__ void emit(const float4* __restrict__ anchors,
                                     const float4* __restrict__ deltas,
                                     int b, int g, u64 key) {
    if (g >= PRE) return;
    unsigned idx = ~(unsigned)(key & 0xffffffffu);
    float sc;
    float4 bx;
    if (key != 0ull && idx < A_N) {
        sc = __uint_as_float((unsigned)(key >> 32));
        bx = decode_clip(anchors[idx], deltas[(size_t)b * A_N + idx]);
    } else {
        sc = 0.0f;
        bx = make_float4(0.f, 0.f, 0.f, 0.f);
    }
    g_box[b * PRE + g] = bx;
    g_sc2[b * PRE + g] = sc;
}

__global__ void k_sort(const float4* __restrict__ anchors,
                       const float4* __restrict__ deltas,
                       const float* __restrict__ scores) {
    __shared__ u64 sh[SORTN];              // 32 KB: filtered list + sort scratch
    __shared__ int hist[NH];               // 8 KB
    __shared__ int ss[256];
    __shared__ int segc[NSEG];
    __shared__ int s_m, s_thr, s_fb;
    const unsigned FULL = 0xffffffffu;
    int b = blockIdx.x;
    int t = threadIdx.x;                   // 1024 threads

    for (int i = t; i < NH; i += 1024) hist[i] = 0;
    if (t < NSEG) segc[t] = g_ccnt[b * NSEG + t];
    if (t == 0) { s_m = 0; s_fb = 0; }
    __syncthreads();
    if (t == 0) {
        int tot = 0, ov = 0;
        for (int s = 0; s < NSEG; s++) { tot += min(segc[s], SEGSZ); ov |= (segc[s] > SEGSZ); }
        s_fb = (ov || tot < PRE) ? 1 : 0;
    }
    __syncthreads();

    if (!s_fb) {
        // -------- normal path: candidates all have s >= PREF --------
        for (int slot = t; slot < NCAND; slot += 1024) {
            int seg = slot >> 8, k = slot & (SEGSZ - 1);
            if (k < min(segc[seg], SEGSZ)) {
                u64 key = g_cand[(size_t)(b * NSEG + seg) * SEGSZ + k];
                float s = __uint_as_float((unsigned)(key >> 32));
                int bk = min((int)((s - PREF) * HSCALE), NH - 1);
                atomicAdd(&hist[bk], 1);
            }
        }
        __syncthreads();
        if (t < 256) {
            int acc = 0, base = NH - 1 - t * 8;
            for (int j = 0; j < 8; j++) acc += hist[base - j];
            ss[t] = acc;
        }
        __syncthreads();
        if (t == 0) {
            int run = 0, thr = 0;
            for (int c = 0; c < 256; c++) {
                if (run + ss[c] >= PRE) {
                    int base = NH - 1 - c * 8;
                    for (int j = 0; j < 8; j++) {
                        run += hist[base - j];
                        if (run >= PRE) { thr = base - j; break; }
                    }
                    break;
                }
                run += ss[c];
            }
            s_thr = thr;
        }
        __syncthreads();
        int thr = s_thr;
        for (int slot = t; slot < NCAND; slot += 1024) {
            int seg = slot >> 8, k = slot & (SEGSZ - 1);
            if (k < min(segc[seg], SEGSZ)) {
                u64 key = g_cand[(size_t)(b * NSEG + seg) * SEGSZ + k];
                float s = __uint_as_float((unsigned)(key >> 32));
                int bk = min((int)((s - PREF) * HSCALE), NH - 1);
                if (bk >= thr) {
                    int pos = atomicAdd(&s_m, 1);
                    if (pos < SORTN) sh[pos] = key;
                }
            }
        }
    } else {
        // -------- cold fallback: rescan all scores (256-bucket hist over [0,1))
        for (int i = t; i < A_N; i += 1024) {
            unsigned w = g_valid[b * NWRD + (i >> 5)];
            if ((w >> (i & 31)) & 1u) {
                float s = scores[(size_t)b * A_N + i];
                int bk = min(max((int)(s * 256.0f), 0), 255);
                atomicAdd(&hist[bk], 1);
            }
        }
        __syncthreads();
        if (t == 0) {
            int run = 0, thr = 0;
            for (int k = 255; k >= 0; k--) {
                run += hist[k];
                if (run >= PRE) { thr = k; break; }
            }
            s_thr = thr;
        }
        __syncthreads();
        int thr = s_thr;
        for (int i = t; i < A_N; i += 1024) {
            unsigned w = g_valid[b * NWRD + (i >> 5)];
            if ((w >> (i & 31)) & 1u) {
                float s = scores[(size_t)b * A_N + i];
                int bk = min(max((int)(s * 256.0f), 0), 255);
                if (bk >= thr) {
                    int pos = atomicAdd(&s_m, 1);
                    if (pos < SORTN)
                        sh[pos] = ((u64)__float_as_uint(s) << 32) | ~(unsigned)i;
                }
            }
        }
    }
    __syncthreads();
    int n = min(s_m, SORTN);

    if (n <= 2048) {
        // ---- fast path: 2048 keys, 2 per thread ----
        int g0 = t * 2;
        u64 v0 = (g0     < n) ? sh[g0]     : 0ull;
        u64 v1 = (g0 + 1 < n) ? sh[g0 + 1] : 0ull;
        __syncthreads();
        for (int k = 2; k <= 2048; k <<= 1) {
            for (int j = k >> 1; j > 0; j >>= 1) {
                bool desc = (g0 & k) == 0;
                if (j >= 64) {
                    sh[g0] = v0; sh[g0 + 1] = v1;
                    __syncthreads();
                    bool kmax = (desc == ((g0 & j) == 0));
                    u64 p0 = sh[g0 ^ j], p1 = sh[(g0 + 1) ^ j];
                    v0 = kmax ? (p0 > v0 ? p0 : v0) : (p0 < v0 ? p0 : v0);
                    v1 = kmax ? (p1 > v1 ? p1 : v1) : (p1 < v1 ? p1 : v1);
                    __syncthreads();
                } else if (j >= 2) {
                    int lm = j >> 1;
                    bool kmax = (desc == ((g0 & j) == 0));
                    u64 p0 = __shfl_xor_sync(FULL, v0, lm);
                    u64 p1 = __shfl_xor_sync(FULL, v1, lm);
                    v0 = kmax ? (p0 > v0 ? p0 : v0) : (p0 < v0 ? p0 : v0);
                    v1 = kmax ? (p1 > v1 ? p1 : v1) : (p1 < v1 ? p1 : v1);
                } else {
                    cex(v0, v1, desc);
                }
            }
        }
        emit(anchors, deltas, b, g0, v0);
        emit(anchors, deltas, b, g0 + 1, v1);
    } else {
        // ---- 4096 keys, 4 per thread ----
        u64 v[4];
        int g0 = t * 4;
        #pragma unroll
        for (int m = 0; m < 4; m++) {
            int g = g0 + m;
            v[m] = (g < n) ? sh[g] : 0ull;
        }
        __syncthreads();
        for (int k = 2; k <= SORTN; k <<= 1) {
            for (int j = k >> 1; j > 0; j >>= 1) {
                if (j >= 128) {
                    #pragma unroll
                    for (int m = 0; m < 4; m++) sh[g0 + m] = v[m];
                    __syncthreads();
                    bool kmax = (((g0 & k) == 0) == ((g0 & j) == 0));
                    #pragma unroll
                    for (int m = 0; m < 4; m++) {
                        u64 pv = sh[(g0 + m) ^ j];
                        v[m] = kmax ? (pv > v[m] ? pv : v[m]) : (pv < v[m] ? pv : v[m]);
                    }
                    __syncthreads();
                } else if (j >= 4) {
                    int lm = j >> 2;
                    bool kmax = (((g0 & k) == 0) == ((g0 & j) == 0));
                    #pragma unroll
                    for (int m = 0; m < 4; m++) {
                        u64 pv = __shfl_xor_sync(FULL, v[m], lm);
                        v[m] = kmax ? (pv > v[m] ? pv : v[m]) : (pv < v[m] ? pv : v[m]);
                    }
                } else if (j == 2) {
                    bool desc = (g0 & k) == 0;
                    cex(v[0], v[2], desc);
                    cex(v[1], v[3], desc);
                } else {
                    if (k == 2) { cex(v[0], v[1], true); cex(v[2], v[3], false); }
                    else {
                        bool desc = (g0 & k) == 0;
                        cex(v[0], v[1], desc);
                        cex(v[2], v[3], desc);
                    }
                }
            }
        }
        #pragma unroll
        for (int m = 0; m < 4; m++) emit(anchors, deltas, b, g0 + m, v[m]);
    }
}

// ---------------- kernel 3: IoU suppression bitmask (upper triangle only) -------
__global__ void k_iou() {
    __shared__ float4 cb[64];
    __shared__ float  ca[64];
    int rowbase = blockIdx.y * 64;
    int colbase = blockIdx.x * 64;
    if (colbase + 63 <= rowbase) return;   // lower-tri words stay 0
    int b = blockIdx.z;
    int t = threadIdx.x;
    int j = colbase + t;
    float4 cj = (j < PRE) ? g_box[b * PRE + j] : make_float4(0.f, 0.f, 0.f, 0.f);
    cb[t] = cj;
    ca[t] = (cj.z - cj.x) * (cj.w - cj.y);
    __syncthreads();
    int i = rowbase + t;
    if (i >= PRE) return;
    float4 bi = g_box[b * PRE + i];
    float  ai = (bi.z - bi.x) * (bi.w - bi.y);
    u64 word = 0ull;
    #pragma unroll 8
    for (int jj = 0; jj < 64; jj++) {
        int jg = colbase + jj;
        if (jg > i && jg < PRE) {
            float4 bb = cb[jj];
            float lx = fmaxf(bi.x, bb.x), ly = fmaxf(bi.y, bb.y);
            float rx = fminf(bi.z, bb.z), ry = fminf(bi.w, bb.w);
            float w = fmaxf(rx - lx, 0.0f), h = fmaxf(ry - ly, 0.0f);
            float inter = w * h;
            float iou = inter / (ai + ca[jj] - inter + 1e-6f);
            if (iou > NMS_THR_F) word |= (1ull << jj);
        }
    }
    g_mask[((size_t)b * MROWS + i) * NW + blockIdx.x] = word;
}

// ---------------- kernel 4: greedy scan + fused output -------------------------
// 64 threads: warp 0 = serial scan over shared, warp 1 = vectorized prefetch.
// Padding rows (2000..2047) have all-zero masks: treated as "kept", no effect.
__global__ void k_nms_out(float* __restrict__ out) {
    __shared__ __align__(16) u64 buf[2][64 * NW];   // 32 KB double buffer
    const int NCH = MROWS / 64;            // 32 full 64-row chunks
    const unsigned FULL = 0xffffffffu;
    int b = blockIdx.x;
    int tid = threadIdx.x;
    int warp = tid >> 5;
    int lane = tid & 31;
    const u64* __restrict__ M = &g_mask[(size_t)b * MROWS * NW];

    // preload chunk 0 (both warps, uint4 vectorized)
    {
        const uint4* src = (const uint4*)M;
        uint4* dst = (uint4*)buf[0];
        for (int i = tid; i < 64 * NW / 2; i += 64) dst[i] = src[i];
    }
    __syncthreads();

    u64 remv = 0ull;                       // warp0: lane t owns removal word t
    for (int c = 0; c < NCH; c++) {
        if (warp == 0) {
            const u64* dp = buf[c & 1];
            u64 cur = __shfl_sync(FULL, remv, c);
            unsigned keptlo = 0, kepthi = 0;
            u64 newcur = 0ull;
            if (lane == 0) {
                unsigned clo = (unsigned)cur, chi = (unsigned)(cur >> 32);
                #pragma unroll
                for (int r = 0; r < 32; r++) {
                    u64 d = dp[r * NW + c];
                    unsigned sel = ((clo >> r) & 1u) - 1u;   // kept -> ~0
                    clo |= (unsigned)d & sel;
                    chi |= (unsigned)(d >> 32) & sel;
                }
                const unsigned* dph = (const unsigned*)dp;   // high words only
                #pragma unroll
                for (int r = 32; r < 64; r++) {
                    unsigned dh = dph[2 * (r * NW + c) + 1];
                    unsigned sel = ((chi >> (r - 32)) & 1u) - 1u;
                    chi |= dh & sel;                         // low half is 0 here
                }
                keptlo = ~clo; kepthi = ~chi;
                newcur = ((u64)chi << 32) | clo;
            }
            unsigned klo = __shfl_sync(FULL, keptlo, 0);
            unsigned khi = __shfl_sync(FULL, kepthi, 0);
            newcur = __shfl_sync(FULL, newcur, 0);
            if (lane == c) remv = newcur;
            #pragma unroll 4
            for (int r = 0; r < 32; r++)
                if ((klo >> r) & 1u) remv |= dp[r * NW + lane];
            #pragma unroll 4
            for (int r = 0; r < 32; r++)
                if ((khi >> r) & 1u) remv |= dp[(r + 32) * NW + lane];
        } else if (c + 1 < NCH) {
            const uint4* src = (const uint4*)&M[(size_t)(c + 1) * 64 * NW];
            uint4* dst = (uint4*)buf[(c + 1) & 1];
            #pragma unroll 4
            for (int i = lane; i < 64 * NW / 2; i += 32) dst[i] = src[i];
        }
        __syncthreads();
    }

    float* ob = &out[(size_t)b * POST * 5];
    for (int i = tid; i < POST * 5; i += 64) ob[i] = 0.0f;
    __syncthreads();

    if (warp == 0) {
        u64 keepw = ~remv;
        if (lane == NW - 1) keepw &= (1ull << (PRE - (NW - 1) * 64)) - 1ull;  // 16 bits
        int pc = __popcll(keepw);
        int inc = pc;
        #pragma unroll
        for (int o = 1; o < 32; o <<= 1) {
            int nn = __shfl_up_sync(FULL, inc, o);
            if (lane >= o) inc += nn;
        }
        int r = inc - pc;                  // exclusive prefix
        u64 w = keepw;
        while (w) {
            int bit = __ffsll((long long)w) - 1;
            w &= w - 1;
            if (r < POST) {
                int i = lane * 64 + bit;
                float4 bx = g_box[b * PRE + i];
                float sc = g_sc2[b * PRE + i];
                float* o = &ob[(size_t)r * 5];
                o[0] = bx.x; o[1] = bx.y; o[2] = bx.z; o[3] = bx.w; o[4] = sc;
            }
            r++;
        }
    }
}

// ---------------- launch ----------------
extern "C" void kernel_launch(void* const* d_in, const int* in_sizes, int n_in,
                              void* d_out, int out_size) {
    const float4* anchors = (const float4*)d_in[0];   // (A,4)
    const float4* deltas  = (const float4*)d_in[1];   // (B,A,4)
    const float*  scores  = (const float*)d_in[2];    // (B,A)
    float* out = (float*)d_out;                        // (B,POST,5)

    k_decode  <<<BATCH * 64, 512>>>(anchors, deltas, scores);
    k_sort    <<<BATCH, 1024>>>(anchors, deltas, scores);
    k_iou     <<<dim3(NW, (PRE + 63) / 64, BATCH), 64>>>();
    k_nms_out <<<BATCH, 64>>>(out);
}

// round 10
// speedup vs baseline: 1.1953x; 1.1953x over previous
#include <cuda_runtime.h>
#include <cstdint>

#define BATCH 16
#define A_N   261888
#define NWRD  8184          // A_N/32 validity words per image
#define PRE   2000
#define MROWS 2048          // padded mask rows (rows >= PRE never written: stay 0)
#define POST  1000
#define SORTN 4096          // max sort size
#define NSEG  64            // chunks per image
#define SEGSZ 256           // candidate slots per chunk
#define NCAND (NSEG * SEGSZ)
#define NH    2048          // selection histogram buckets over [PREF, 1)
#define NW    32            // 32 x uint64 words cover 2048 bits
#define IMGF      1024.0f
#define NMS_THR_F 0.7f
#define MIN_SZ_F  16.0f
#define PREF      0.98f
#define HSCALE    102400.0f // NH / (1 - PREF)

typedef unsigned long long u64;

// ---------------- device scratch ----------------
__device__ unsigned g_valid[BATCH * NWRD];
__device__ int    g_ccnt[BATCH * NSEG];        // written unconditionally each launch
__device__ u64    g_cand[BATCH * NCAND];
__device__ float4 g_box[BATCH * PRE];
__device__ float  g_sc2[BATCH * PRE];
__device__ u64    g_mask[BATCH * MROWS * NW];  // lower-tri + padding rows: always 0

// ---------------- fast exp: FMA pipe only, ~5e-9 rel err ----------------
__device__ __forceinline__ float fast_exp(float x) {
    x = fmaxf(x, -80.0f);
    float z = fmaf(x, 1.4426950408889634f, 12582912.0f);
    float nf = z - 12582912.0f;
    int   ni = __float_as_int(z) - 0x4B400000;
    float t = fmaf(nf, -0.693145751953125f, x);
    t = fmaf(nf, -1.42860677e-6f, t);
    float p = 1.9841270e-4f;
    p = fmaf(p, t, 1.3888889e-3f);
    p = fmaf(p, t, 8.3333338e-3f);
    p = fmaf(p, t, 4.1666668e-2f);
    p = fmaf(p, t, 1.6666667e-1f);
    p = fmaf(p, t, 5.0e-1f);
    p = fmaf(p, t, 1.0f);
    p = fmaf(p, t, 1.0f);
    return p * __int_as_float((ni + 127) << 23);
}

__device__ __forceinline__ float4 decode_clip(const float4 a, const float4 d) {
    float aw = a.z - a.x;
    float ah = a.w - a.y;
    float ax = a.x + 0.5f * aw;
    float ay = a.y + 0.5f * ah;
    float dw = fminf(d.z, 4.0f);
    float dh = fminf(d.w, 4.0f);
    float px = d.x * aw + ax;
    float py = d.y * ah + ay;
    float pw = fast_exp(dw) * aw;
    float ph = fast_exp(dh) * ah;
    float x1 = fminf(fmaxf(px - 0.5f * pw, 0.0f), IMGF);
    float y1 = fminf(fmaxf(py - 0.5f * ph, 0.0f), IMGF);
    float x2 = fminf(fmaxf(px + 0.5f * pw, 0.0f), IMGF);
    float y2 = fminf(fmaxf(py + 0.5f * ph, 0.0f), IMGF);
    return make_float4(x1, y1, x2, y2);
}

// ---------------- kernel 1: decode + validity bitmap + prefilter collect --------
__global__ void k_decode(const float4* __restrict__ anchors,
                         const float4* __restrict__ deltas,
                         const float* __restrict__ scores) {
    __shared__ int s_cnt;
    const unsigned FULL = 0xffffffffu;
    int b = blockIdx.x >> 6;
    int chunk = blockIdx.x & 63;
    int start = chunk * 4096;
    int end = min(start + 4096, A_N);      // last chunk: 3840 (multiple of 32)
    int tid = threadIdx.x;
    if (tid == 0) s_cnt = 0;
    __syncthreads();
    int   li[8];
    float lv[8];
    int c = 0;
    for (int i = start + tid; i < end; i += blockDim.x) {
        float4 a = anchors[i];
        float4 d = deltas[(size_t)b * A_N + i];
        float  s = scores[(size_t)b * A_N + i];
        float4 bx = decode_clip(a, d);
        bool valid = (bx.z - bx.x >= MIN_SZ_F) && (bx.w - bx.y >= MIN_SZ_F);
        unsigned m = __ballot_sync(FULL, valid);
        if ((tid & 31) == 0) g_valid[b * NWRD + (i >> 5)] = m;
        if (valid && s >= PREF && c < 8) { li[c] = i; lv[c] = s; c++; }
    }
    int ofs = 0;
    if (c) ofs = atomicAdd(&s_cnt, c);     // shared atomic only
    for (int k = 0; k < c; k++) {
        int pos = ofs + k;
        if (pos < SEGSZ) {
            unsigned lo = ~(unsigned)li[k];            // lower index wins ties
            g_cand[(size_t)(b * NSEG + chunk) * SEGSZ + pos] =
                ((u64)__float_as_uint(lv[k]) << 32) | lo;
        }
    }
    __syncthreads();
    if (tid == 0) g_ccnt[b * NSEG + chunk] = s_cnt;    // raw count, every launch
}

// ---------------- kernel 2: select top-PRE + bitonic sort (desc) + gather -------
__device__ __forceinline__ void cex(u64& a, u64& b, bool desc) {
    bool sw = desc ? (a < b) : (a > b);
    if (sw) { u64 t = a; a = b; b = t; }
}

__device__ __forceinline__ void emit(const float4* __restrict__ anchors,
                                     const float4* __restrict__ deltas,
                                     int b, int g, u64 key) {
    if (g >= PRE) return;
    unsigned idx = ~(unsigned)(key & 0xffffffffu);
    float sc;
    float4 bx;
    if (key != 0ull && idx < A_N) {
        sc = __uint_as_float((unsigned)(key >> 32));
        bx = decode_clip(anchors[idx], deltas[(size_t)b * A_N + idx]);
    } else {
        sc = 0.0f;
        bx = make_float4(0.f, 0.f, 0.f, 0.f);
    }
    g_box[b * PRE + g] = bx;
    g_sc2[b * PRE + g] = sc;
}

__global__ void k_sort(const float4* __restrict__ anchors,
                       const float4* __restrict__ deltas,
                       const float* __restrict__ scores) {
    __shared__ u64 sh[SORTN];              // 32 KB: filtered list + sort scratch
    __shared__ int hist[NH];               // 8 KB
    __shared__ int ss[256];
    __shared__ int segc[NSEG];
    __shared__ int s_m, s_thr, s_fb;
    const unsigned FULL = 0xffffffffu;
    int b = blockIdx.x;
    int t = threadIdx.x;                   // 1024 threads

    for (int i = t; i < NH; i += 1024) hist[i] = 0;
    if (t < NSEG) segc[t] = g_ccnt[b * NSEG + t];
    if (t == 0) { s_m = 0; s_fb = 0; }
    __syncthreads();
    if (t == 0) {
        int tot = 0, ov = 0;
        for (int s = 0; s < NSEG; s++) { tot += min(segc[s], SEGSZ); ov |= (segc[s] > SEGSZ); }
        s_fb = (ov || tot < PRE) ? 1 : 0;
    }
    __syncthreads();

    if (!s_fb) {
        // -------- normal path: candidates all have s >= PREF --------
        for (int slot = t; slot < NCAND; slot += 1024) {
            int seg = slot >> 8, k = slot & (SEGSZ - 1);
            if (k < min(segc[seg], SEGSZ)) {
                u64 key = g_cand[(size_t)(b * NSEG + seg) * SEGSZ + k];
                float s = __uint_as_float((unsigned)(key >> 32));
                int bk = min((int)((s - PREF) * HSCALE), NH - 1);
                atomicAdd(&hist[bk], 1);
            }
        }
        __syncthreads();
        if (t < 256) {
            int acc = 0, base = NH - 1 - t * 8;
            for (int j = 0; j < 8; j++) acc += hist[base - j];
            ss[t] = acc;
        }
        __syncthreads();
        if (t == 0) {
            int run = 0, thr = 0;
            for (int c = 0; c < 256; c++) {
                if (run + ss[c] >= PRE) {
                    int base = NH - 1 - c * 8;
                    for (int j = 0; j < 8; j++) {
                        run += hist[base - j];
                        if (run >= PRE) { thr = base - j; break; }
                    }
                    break;
                }
                run += ss[c];
            }
            s_thr = thr;
        }
        __syncthreads();
        int thr = s_thr;
        for (int slot = t; slot < NCAND; slot += 1024) {
            int seg = slot >> 8, k = slot & (SEGSZ - 1);
            if (k < min(segc[seg], SEGSZ)) {
                u64 key = g_cand[(size_t)(b * NSEG + seg) * SEGSZ + k];
                float s = __uint_as_float((unsigned)(key >> 32));
                int bk = min((int)((s - PREF) * HSCALE), NH - 1);
                if (bk >= thr) {
                    int pos = atomicAdd(&s_m, 1);
                    if (pos < SORTN) sh[pos] = key;
                }
            }
        }
    } else {
        // -------- cold fallback: rescan all scores (256-bucket hist over [0,1))
        for (int i = t; i < A_N; i += 1024) {
            unsigned w = g_valid[b * NWRD + (i >> 5)];
            if ((w >> (i & 31)) & 1u) {
                float s = scores[(size_t)b * A_N + i];
                int bk = min(max((int)(s * 256.0f), 0), 255);
                atomicAdd(&hist[bk], 1);
            }
        }
        __syncthreads();
        if (t == 0) {
            int run = 0, thr = 0;
            for (int k = 255; k >= 0; k--) {
                run += hist[k];
                if (run >= PRE) { thr = k; break; }
            }
            s_thr = thr;
        }
        __syncthreads();
        int thr = s_thr;
        for (int i = t; i < A_N; i += 1024) {
            unsigned w = g_valid[b * NWRD + (i >> 5)];
            if ((w >> (i & 31)) & 1u) {
                float s = scores[(size_t)b * A_N + i];
                int bk = min(max((int)(s * 256.0f), 0), 255);
                if (bk >= thr) {
                    int pos = atomicAdd(&s_m, 1);
                    if (pos < SORTN)
                        sh[pos] = ((u64)__float_as_uint(s) << 32) | ~(unsigned)i;
                }
            }
        }
    }
    __syncthreads();
    int n = min(s_m, SORTN);

    if (n <= 2048) {
        // ---- fast path: 2048 keys, 2 per thread ----
        int g0 = t * 2;
        u64 v0 = (g0     < n) ? sh[g0]     : 0ull;
        u64 v1 = (g0 + 1 < n) ? sh[g0 + 1] : 0ull;
        __syncthreads();
        for (int k = 2; k <= 2048; k <<= 1) {
            for (int j = k >> 1; j > 0; j >>= 1) {
                bool desc = (g0 & k) == 0;
                if (j >= 64) {
                    sh[g0] = v0; sh[g0 + 1] = v1;
                    __syncthreads();
                    bool kmax = (desc == ((g0 & j) == 0));
                    u64 p0 = sh[g0 ^ j], p1 = sh[(g0 + 1) ^ j];
                    v0 = kmax ? (p0 > v0 ? p0 : v0) : (p0 < v0 ? p0 : v0);
                    v1 = kmax ? (p1 > v1 ? p1 : v1) : (p1 < v1 ? p1 : v1);
                    __syncthreads();
                } else if (j >= 2) {
                    int lm = j >> 1;
                    bool kmax = (desc == ((g0 & j) == 0));
                    u64 p0 = __shfl_xor_sync(FULL, v0, lm);
                    u64 p1 = __shfl_xor_sync(FULL, v1, lm);
                    v0 = kmax ? (p0 > v0 ? p0 : v0) : (p0 < v0 ? p0 : v0);
                    v1 = kmax ? (p1 > v1 ? p1 : v1) : (p1 < v1 ? p1 : v1);
                } else {
                    cex(v0, v1, desc);
                }
            }
        }
        emit(anchors, deltas, b, g0, v0);
        emit(anchors, deltas, b, g0 + 1, v1);
    } else {
        // ---- 4096 keys, 4 per thread ----
        u64 v[4];
        int g0 = t * 4;
        #pragma unroll
        for (int m = 0; m < 4; m++) {
            int g = g0 + m;
            v[m] = (g < n) ? sh[g] : 0ull;
        }
        __syncthreads();
        for (int k = 2; k <= SORTN; k <<= 1) {
            for (int j = k >> 1; j > 0; j >>= 1) {
                if (j >= 128) {
                    #pragma unroll
                    for (int m = 0; m < 4; m++) sh[g0 + m] = v[m];
                    __syncthreads();
                    bool kmax = (((g0 & k) == 0) == ((g0 & j) == 0));
                    #pragma unroll
                    for (int m = 0; m < 4; m++) {
                        u64 pv = sh[(g0 + m) ^ j];
                        v[m] = kmax ? (pv > v[m] ? pv : v[m]) : (pv < v[m] ? pv : v[m]);
                    }
                    __syncthreads();
                } else if (j >= 4) {
                    int lm = j >> 2;
                    bool kmax = (((g0 & k) == 0) == ((g0 & j) == 0));
                    #pragma unroll
                    for (int m = 0; m < 4; m++) {
                        u64 pv = __shfl_xor_sync(FULL, v[m], lm);
                        v[m] = kmax ? (pv > v[m] ? pv : v[m]) : (pv < v[m] ? pv : v[m]);
                    }
                } else if (j == 2) {
                    bool desc = (g0 & k) == 0;
                    cex(v[0], v[2], desc);
                    cex(v[1], v[3], desc);
                } else {
                    if (k == 2) { cex(v[0], v[1], true); cex(v[2], v[3], false); }
                    else {
                        bool desc = (g0 & k) == 0;
                        cex(v[0], v[1], desc);
                        cex(v[2], v[3], desc);
                    }
                }
            }
        }
        #pragma unroll
        for (int m = 0; m < 4; m++) emit(anchors, deltas, b, g0 + m, v[m]);
    }
}

// ---------------- kernel 3: IoU suppression bitmask (upper triangle only) -------
__global__ void k_iou() {
    __shared__ float4 cb[64];
    __shared__ float  ca[64];
    int rowbase = blockIdx.y * 64;
    int colbase = blockIdx.x * 64;
    if (colbase + 63 <= rowbase) return;   // lower-tri words stay 0
    int b = blockIdx.z;
    int t = threadIdx.x;
    int j = colbase + t;
    float4 cj = (j < PRE) ? g_box[b * PRE + j] : make_float4(0.f, 0.f, 0.f, 0.f);
    cb[t] = cj;
    ca[t] = (cj.z - cj.x) * (cj.w - cj.y);
    __syncthreads();
    int i = rowbase + t;
    if (i >= PRE) return;
    float4 bi = g_box[b * PRE + i];
    float  ai = (bi.z - bi.x) * (bi.w - bi.y);
    u64 word = 0ull;
    #pragma unroll 8
    for (int jj = 0; jj < 64; jj++) {
        int jg = colbase + jj;
        if (jg > i && jg < PRE) {
            float4 bb = cb[jj];
            float lx = fmaxf(bi.x, bb.x), ly = fmaxf(bi.y, bb.y);
            float rx = fminf(bi.z, bb.z), ry = fminf(bi.w, bb.w);
            float w = fmaxf(rx - lx, 0.0f), h = fmaxf(ry - ly, 0.0f);
            float inter = w * h;
            float iou = inter / (ai + ca[jj] - inter + 1e-6f);
            if (iou > NMS_THR_F) word |= (1ull << jj);
        }
    }
    g_mask[((size_t)b * MROWS + i) * NW + blockIdx.x] = word;
}

// ---------------- kernel 4: greedy scan + fused output -------------------------
// 256 threads: warp 0 = serial scan over shared, warps 1-7 = vectorized prefetch.
// Padding rows (2000..2047) have all-zero masks: treated as "kept", no effect.
__global__ void k_nms_out(float* __restrict__ out) {
    __shared__ __align__(16) u64 buf[2][64 * NW];   // 32 KB double buffer
    const int NCH = MROWS / 64;            // 32 full 64-row chunks
    const unsigned FULL = 0xffffffffu;
    int b = blockIdx.x;
    int tid = threadIdx.x;
    int warp = tid >> 5;
    int lane = tid & 31;
    const u64* __restrict__ M = &g_mask[(size_t)b * MROWS * NW];

    // preload chunk 0 (all threads, uint4 vectorized)
    {
        const uint4* src = (const uint4*)M;
        uint4* dst = (uint4*)buf[0];
        for (int i = tid; i < 64 * NW / 2; i += 256) dst[i] = src[i];
    }
    __syncthreads();

    u64 remv = 0ull;                       // warp0: lane t owns removal word t
    for (int c = 0; c < NCH; c++) {
        if (warp == 0) {
            const u64* dp = buf[c & 1];
            u64 cur = __shfl_sync(FULL, remv, c);
            unsigned keptlo = 0, kepthi = 0;
            if (lane == 0) {
                unsigned clo = (unsigned)cur, chi = (unsigned)(cur >> 32);
                #pragma unroll
                for (int r = 0; r < 32; r++) {
                    u64 d = dp[r * NW + c];
                    unsigned sel = ((clo >> r) & 1u) - 1u;   // kept -> ~0
                    clo |= (unsigned)d & sel;
                    chi |= (unsigned)(d >> 32) & sel;
                }
                const unsigned* dph = (const unsigned*)dp;   // high words only
                #pragma unroll
                for (int r = 32; r < 64; r++) {
                    unsigned dh = dph[2 * (r * NW + c) + 1];
                    unsigned sel = ((chi >> (r - 32)) & 1u) - 1u;
                    chi |= dh & sel;                         // low half is 0 here
                }
                keptlo = ~clo; kepthi = ~chi;
            }
            unsigned klo = __shfl_sync(FULL, keptlo, 0);
            unsigned khi = __shfl_sync(FULL, kepthi, 0);
            if (lane == c) remv = ((u64)(~khi) << 32) | (u64)(~klo);
            // branchless OR of kept rows, 4 independent accumulators
            u64 a0 = 0, a1 = 0, a2 = 0, a3 = 0;
            #pragma unroll
            for (int r = 0; r < 32; r += 4) {
                a0 |= dp[(r    ) * NW + lane] & (u64)(-(long long)((klo >> (r    )) & 1u));
                a1 |= dp[(r + 1) * NW + lane] & (u64)(-(long long)((klo >> (r + 1)) & 1u));
                a2 |= dp[(r + 2) * NW + lane] & (u64)(-(long long)((klo >> (r + 2)) & 1u));
                a3 |= dp[(r + 3) * NW + lane] & (u64)(-(long long)((klo >> (r + 3)) & 1u));
            }
            #pragma unroll
            for (int r = 0; r < 32; r += 4) {
                a0 |= dp[(r + 32) * NW + lane] & (u64)(-(long long)((khi >> (r    )) & 1u));
                a1 |= dp[(r + 33) * NW + lane] & (u64)(-(long long)((khi >> (r + 1)) & 1u));
                a2 |= dp[(r + 34) * NW + lane] & (u64)(-(long long)((khi >> (r + 2)) & 1u));
                a3 |= dp[(r + 35) * NW + lane] & (u64)(-(long long)((khi >> (r + 3)) & 1u));
            }
            remv |= (a0 | a1) | (a2 | a3);
        } else if (c + 1 < NCH) {
            const uint4* src = (const uint4*)&M[(size_t)(c + 1) * 64 * NW];
            uint4* dst = (uint4*)buf[(c + 1) & 1];
            for (int i = tid - 32; i < 64 * NW / 2; i += 224) dst[i] = src[i];
        }
        __syncthreads();
    }

    float* ob = &out[(size_t)b * POST * 5];
    for (int i = tid; i < POST * 5; i += 256) ob[i] = 0.0f;
    __syncthreads();

    if (warp == 0) {
        u64 keepw = ~remv;
        if (lane == NW - 1) keepw &= (1ull << (PRE - (NW - 1) * 64)) - 1ull;  // 16 bits
        int pc = __popcll(keepw);
        int inc = pc;
        #pragma unroll
        for (int o = 1; o < 32; o <<= 1) {
            int nn = __shfl_up_sync(FULL, inc, o);
            if (lane >= o) inc += nn;
        }
        int r = inc - pc;                  // exclusive prefix
        u64 w = keepw;
        while (w) {
            int bit = __ffsll((long long)w) - 1;
            w &= w - 1;
            if (r < POST) {
                int i = lane * 64 + bit;
                float4 bx = g_box[b * PRE + i];
                float sc = g_sc2[b * PRE + i];
                float* o = &ob[(size_t)r * 5];
                o[0] = bx.x; o[1] = bx.y; o[2] = bx.z; o[3] = bx.w; o[4] = sc;
            }
            r++;
        }
    }
}

// ---------------- launch ----------------
extern "C" void kernel_launch(void* const* d_in, const int* in_sizes, int n_in,
                              void* d_out, int out_size) {
    const float4* anchors = (const float4*)d_in[0];   // (A,4)
    const float4* deltas  = (const float4*)d_in[1];   // (B,A,4)
    const float*  scores  = (const float*)d_in[2];    // (B,A)
    float* out = (float*)d_out;                        // (B,POST,5)

    k_decode  <<<BATCH * 64, 512>>>(anchors, deltas, scores);
    k_sort    <<<BATCH, 1024>>>(anchors, deltas, scores);
    k_iou     <<<dim3(NW, (PRE + 63) / 64, BATCH), 64>>>();
    k_nms_out <<<BATCH, 256>>>(out);
}

// round 11
// speedup vs baseline: 1.4511x; 1.2140x over previous
#include <cuda_runtime.h>
#include <cstdint>

#define BATCH 16
#define A_N   261888
#define NWRD  8184          // A_N/32 validity words per image
#define PRE   2000
#define MROWS 2048          // padded mask rows (rows >= PRE never written: stay 0)
#define POST  1000
#define SORTN 4096          // max sort size
#define NSEG  64            // chunks per image
#define SEGSZ 256           // candidate slots per chunk
#define NCAND (NSEG * SEGSZ)
#define NH    2048          // selection histogram buckets over [PREF, 1)
#define NW    32            // 32 x uint64 words cover 2048 bits
#define IMGF      1024.0f
#define NMS_THR_F 0.7f
#define MIN_SZ_F  16.0f
#define PREF      0.98f
#define HSCALE    102400.0f // NH / (1 - PREF)

typedef unsigned long long u64;

// ---------------- device scratch ----------------
__device__ unsigned g_valid[BATCH * NWRD];
__device__ int    g_ccnt[BATCH * NSEG];        // written unconditionally each launch
__device__ u64    g_cand[BATCH * NCAND];
__device__ float4 g_box[BATCH * PRE];
__device__ float  g_sc2[BATCH * PRE];
__device__ u64    g_mask[BATCH * MROWS * NW];  // lower-tri + padding rows: always 0

// ---------------- fast exp: FMA pipe only, ~5e-9 rel err ----------------
__device__ __forceinline__ float fast_exp(float x) {
    x = fmaxf(x, -80.0f);
    float z = fmaf(x, 1.4426950408889634f, 12582912.0f);
    float nf = z - 12582912.0f;
    int   ni = __float_as_int(z) - 0x4B400000;
    float t = fmaf(nf, -0.693145751953125f, x);
    t = fmaf(nf, -1.42860677e-6f, t);
    float p = 1.9841270e-4f;
    p = fmaf(p, t, 1.3888889e-3f);
    p = fmaf(p, t, 8.3333338e-3f);
    p = fmaf(p, t, 4.1666668e-2f);
    p = fmaf(p, t, 1.6666667e-1f);
    p = fmaf(p, t, 5.0e-1f);
    p = fmaf(p, t, 1.0f);
    p = fmaf(p, t, 1.0f);
    return p * __int_as_float((ni + 127) << 23);
}

__device__ __forceinline__ float4 decode_clip(const float4 a, const float4 d) {
    float aw = a.z - a.x;
    float ah = a.w - a.y;
    float ax = a.x + 0.5f * aw;
    float ay = a.y + 0.5f * ah;
    float dw = fminf(d.z, 4.0f);
    float dh = fminf(d.w, 4.0f);
    float px = d.x * aw + ax;
    float py = d.y * ah + ay;
    float pw = fast_exp(dw) * aw;
    float ph = fast_exp(dh) * ah;
    float x1 = fminf(fmaxf(px - 0.5f * pw, 0.0f), IMGF);
    float y1 = fminf(fmaxf(py - 0.5f * ph, 0.0f), IMGF);
    float x2 = fminf(fmaxf(px + 0.5f * pw, 0.0f), IMGF);
    float y2 = fminf(fmaxf(py + 0.5f * ph, 0.0f), IMGF);
    return make_float4(x1, y1, x2, y2);
}

// ---------------- kernel 1: decode + validity bitmap + prefilter collect --------
__global__ void k_decode(const float4* __restrict__ anchors,
                         const float4* __restrict__ deltas,
                         const float* __restrict__ scores) {
    __shared__ int s_cnt;
    const unsigned FULL = 0xffffffffu;
    int b = blockIdx.x >> 6;
    int chunk = blockIdx.x & 63;
    int start = chunk * 4096;
    int end = min(start + 4096, A_N);      // last chunk: 3840 (multiple of 32)
    int tid = threadIdx.x;
    if (tid == 0) s_cnt = 0;
    __syncthreads();
    int   li[8];
    float lv[8];
    int c = 0;
    for (int i = start + tid; i < end; i += blockDim.x) {
        float4 a = anchors[i];
        float4 d = deltas[(size_t)b * A_N + i];
        float  s = scores[(size_t)b * A_N + i];
        float4 bx = decode_clip(a, d);
        bool valid = (bx.z - bx.x >= MIN_SZ_F) && (bx.w - bx.y >= MIN_SZ_F);
        unsigned m = __ballot_sync(FULL, valid);
        if ((tid & 31) == 0) g_valid[b * NWRD + (i >> 5)] = m;
        if (valid && s >= PREF && c < 8) { li[c] = i; lv[c] = s; c++; }
    }
    int ofs = 0;
    if (c) ofs = atomicAdd(&s_cnt, c);     // shared atomic only
    for (int k = 0; k < c; k++) {
        int pos = ofs + k;
        if (pos < SEGSZ) {
            unsigned lo = ~(unsigned)li[k];            // lower index wins ties
            g_cand[(size_t)(b * NSEG + chunk) * SEGSZ + pos] =
                ((u64)__float_as_uint(lv[k]) << 32) | lo;
        }
    }
    __syncthreads();
    if (tid == 0) g_ccnt[b * NSEG + chunk] = s_cnt;    // raw count, every launch
}

// ---------------- kernel 2: select top-PRE + bitonic sort (desc) + gather -------
__device__ __forceinline__ void cex(u64& a, u64& b, bool desc) {
    bool sw = desc ? (a < b) : (a > b);
    if (sw) { u64 t = a; a = b; b = t; }
}

__device__ __forceinline__ void emit(const float4* __restrict__ anchors,
                                     const float4* __restrict__ deltas,
                                     int b, int g, u64 key) {
    if (g >= PRE) return;
    unsigned idx = ~(unsigned)(key & 0xffffffffu);
    float sc;
    float4 bx;
    if (key != 0ull && idx < A_N) {
        sc = __uint_as_float((unsigned)(key >> 32));
        bx = decode_clip(anchors[idx], deltas[(size_t)b * A_N + idx]);
    } else {
        sc = 0.0f;
        bx = make_float4(0.f, 0.f, 0.f, 0.f);
    }
    g_box[b * PRE + g] = bx;
    g_sc2[b * PRE + g] = sc;
}

__global__ void k_sort(const float4* __restrict__ anchors,
                       const float4* __restrict__ deltas,
                       const float* __restrict__ scores) {
    __shared__ u64 sh[SORTN];              // 32 KB: filtered list + sort scratch
    __shared__ int hist[NH];               // 8 KB
    __shared__ int ss[256];
    __shared__ int segc[NSEG];
    __shared__ int s_m, s_thr, s_fb;
    const unsigned FULL = 0xffffffffu;
    int b = blockIdx.x;
    int t = threadIdx.x;                   // 1024 threads

    for (int i = t; i < NH; i += 1024) hist[i] = 0;
    if (t < NSEG) segc[t] = g_ccnt[b * NSEG + t];
    if (t == 0) { s_m = 0; s_fb = 0; }
    __syncthreads();
    if (t == 0) {
        int tot = 0, ov = 0;
        for (int s = 0; s < NSEG; s++) { tot += min(segc[s], SEGSZ); ov |= (segc[s] > SEGSZ); }
        s_fb = (ov || tot < PRE) ? 1 : 0;
    }
    __syncthreads();

    if (!s_fb) {
        // -------- normal path: candidates all have s >= PREF --------
        for (int slot = t; slot < NCAND; slot += 1024) {
            int seg = slot >> 8, k = slot & (SEGSZ - 1);
            if (k < min(segc[seg], SEGSZ)) {
                u64 key = g_cand[(size_t)(b * NSEG + seg) * SEGSZ + k];
                float s = __uint_as_float((unsigned)(key >> 32));
                int bk = min((int)((s - PREF) * HSCALE), NH - 1);
                atomicAdd(&hist[bk], 1);
            }
        }
        __syncthreads();
        if (t < 256) {
            int acc = 0, base = NH - 1 - t * 8;
            for (int j = 0; j < 8; j++) acc += hist[base - j];
            ss[t] = acc;
        }
        __syncthreads();
        if (t == 0) {
            int run = 0, thr = 0;
            for (int c = 0; c < 256; c++) {
                if (run + ss[c] >= PRE) {
                    int base = NH - 1 - c * 8;
                    for (int j = 0; j < 8; j++) {
                        run += hist[base - j];
                        if (run >= PRE) { thr = base - j; break; }
                    }
                    break;
                }
                run += ss[c];
            }
            s_thr = thr;
        }
        __syncthreads();
        int thr = s_thr;
        for (int slot = t; slot < NCAND; slot += 1024) {
            int seg = slot >> 8, k = slot & (SEGSZ - 1);
            if (k < min(segc[seg], SEGSZ)) {
                u64 key = g_cand[(size_t)(b * NSEG + seg) * SEGSZ + k];
                float s = __uint_as_float((unsigned)(key >> 32));
                int bk = min((int)((s - PREF) * HSCALE), NH - 1);
                if (bk >= thr) {
                    int pos = atomicAdd(&s_m, 1);
                    if (pos < SORTN) sh[pos] = key;
                }
            }
        }
    } else {
        // -------- cold fallback: rescan all scores (256-bucket hist over [0,1))
        for (int i = t; i < A_N; i += 1024) {
            unsigned w = g_valid[b * NWRD + (i >> 5)];
            if ((w >> (i & 31)) & 1u) {
                float s = scores[(size_t)b * A_N + i];
                int bk = min(max((int)(s * 256.0f), 0), 255);
                atomicAdd(&hist[bk], 1);
            }
        }
        __syncthreads();
        if (t == 0) {
            int run = 0, thr = 0;
            for (int k = 255; k >= 0; k--) {
                run += hist[k];
                if (run >= PRE) { thr = k; break; }
            }
            s_thr = thr;
        }
        __syncthreads();
        int thr = s_thr;
        for (int i = t; i < A_N; i += 1024) {
            unsigned w = g_valid[b * NWRD + (i >> 5)];
            if ((w >> (i & 31)) & 1u) {
                float s = scores[(size_t)b * A_N + i];
                int bk = min(max((int)(s * 256.0f), 0), 255);
                if (bk >= thr) {
                    int pos = atomicAdd(&s_m, 1);
                    if (pos < SORTN)
                        sh[pos] = ((u64)__float_as_uint(s) << 32) | ~(unsigned)i;
                }
            }
        }
    }
    __syncthreads();
    int n = min(s_m, SORTN);

    if (n <= 2048) {
        // ---- fast path: 2048 keys, 2 per thread ----
        int g0 = t * 2;
        u64 v0 = (g0     < n) ? sh[g0]     : 0ull;
        u64 v1 = (g0 + 1 < n) ? sh[g0 + 1] : 0ull;
        __syncthreads();
        for (int k = 2; k <= 2048; k <<= 1) {
            for (int j = k >> 1; j > 0; j >>= 1) {
                bool desc = (g0 & k) == 0;
                if (j >= 64) {
                    sh[g0] = v0; sh[g0 + 1] = v1;
                    __syncthreads();
                    bool kmax = (desc == ((g0 & j) == 0));
                    u64 p0 = sh[g0 ^ j], p1 = sh[(g0 + 1) ^ j];
                    v0 = kmax ? (p0 > v0 ? p0 : v0) : (p0 < v0 ? p0 : v0);
                    v1 = kmax ? (p1 > v1 ? p1 : v1) : (p1 < v1 ? p1 : v1);
                    __syncthreads();
                } else if (j >= 2) {
                    int lm = j >> 1;
                    bool kmax = (desc == ((g0 & j) == 0));
                    u64 p0 = __shfl_xor_sync(FULL, v0, lm);
                    u64 p1 = __shfl_xor_sync(FULL, v1, lm);
                    v0 = kmax ? (p0 > v0 ? p0 : v0) : (p0 < v0 ? p0 : v0);
                    v1 = kmax ? (p1 > v1 ? p1 : v1) : (p1 < v1 ? p1 : v1);
                } else {
                    cex(v0, v1, desc);
                }
            }
        }
        emit(anchors, deltas, b, g0, v0);
        emit(anchors, deltas, b, g0 + 1, v1);
    } else {
        // ---- 4096 keys, 4 per thread ----
        u64 v[4];
        int g0 = t * 4;
        #pragma unroll
        for (int m = 0; m < 4; m++) {
            int g = g0 + m;
            v[m] = (g < n) ? sh[g] : 0ull;
        }
        __syncthreads();
        for (int k = 2; k <= SORTN; k <<= 1) {
            for (int j = k >> 1; j > 0; j >>= 1) {
                if (j >= 128) {
                    #pragma unroll
                    for (int m = 0; m < 4; m++) sh[g0 + m] = v[m];
                    __syncthreads();
                    bool kmax = (((g0 & k) == 0) == ((g0 & j) == 0));
                    #pragma unroll
                    for (int m = 0; m < 4; m++) {
                        u64 pv = sh[(g0 + m) ^ j];
                        v[m] = kmax ? (pv > v[m] ? pv : v[m]) : (pv < v[m] ? pv : v[m]);
                    }
                    __syncthreads();
                } else if (j >= 4) {
                    int lm = j >> 2;
                    bool kmax = (((g0 & k) == 0) == ((g0 & j) == 0));
                    #pragma unroll
                    for (int m = 0; m < 4; m++) {
                        u64 pv = __shfl_xor_sync(FULL, v[m], lm);
                        v[m] = kmax ? (pv > v[m] ? pv : v[m]) : (pv < v[m] ? pv : v[m]);
                    }
                } else if (j == 2) {
                    bool desc = (g0 & k) == 0;
                    cex(v[0], v[2], desc);
                    cex(v[1], v[3], desc);
                } else {
                    if (k == 2) { cex(v[0], v[1], true); cex(v[2], v[3], false); }
                    else {
                        bool desc = (g0 & k) == 0;
                        cex(v[0], v[1], desc);
                        cex(v[2], v[3], desc);
                    }
                }
            }
        }
        #pragma unroll
        for (int m = 0; m < 4; m++) emit(anchors, deltas, b, g0 + m, v[m]);
    }
}

// ---------------- kernel 3: IoU suppression bitmask (upper triangle only) -------
__global__ void k_iou() {
    __shared__ float4 cb[64];
    __shared__ float  ca[64];
    int rowbase = blockIdx.y * 64;
    int colbase = blockIdx.x * 64;
    if (colbase + 63 <= rowbase) return;   // lower-tri words stay 0
    int b = blockIdx.z;
    int t = threadIdx.x;
    int j = colbase + t;
    float4 cj = (j < PRE) ? g_box[b * PRE + j] : make_float4(0.f, 0.f, 0.f, 0.f);
    cb[t] = cj;
    ca[t] = (cj.z - cj.x) * (cj.w - cj.y);
    __syncthreads();
    int i = rowbase + t;
    if (i >= PRE) return;
    float4 bi = g_box[b * PRE + i];
    float  ai = (bi.z - bi.x) * (bi.w - bi.y);
    u64 word = 0ull;
    #pragma unroll 8
    for (int jj = 0; jj < 64; jj++) {
        int jg = colbase + jj;
        if (jg > i && jg < PRE) {
            float4 bb = cb[jj];
            float lx = fmaxf(bi.x, bb.x), ly = fmaxf(bi.y, bb.y);
            float rx = fminf(bi.z, bb.z), ry = fminf(bi.w, bb.w);
            float w = fmaxf(rx - lx, 0.0f), h = fmaxf(ry - ly, 0.0f);
            float inter = w * h;
            float iou = inter / (ai + ca[jj] - inter + 1e-6f);
            if (iou > NMS_THR_F) word |= (1ull << jj);
        }
    }
    g_mask[((size_t)b * MROWS + i) * NW + blockIdx.x] = word;
}

// ---------------- kernel 4: greedy scan + fused output -------------------------
// 512 threads: warp 0 = serial scan (decision words batched into registers),
// warps 1-15 = vectorized double-buffer prefetch.
// Padding rows (2000..2047) have all-zero masks: treated as "kept", no effect.
__global__ void __launch_bounds__(512) k_nms_out(float* __restrict__ out) {
    __shared__ __align__(16) u64 buf[2][64 * NW];   // 32 KB double buffer
    const int NCH = MROWS / 64;            // 32 full 64-row chunks
    const unsigned FULL = 0xffffffffu;
    int b = blockIdx.x;
    int tid = threadIdx.x;
    int warp = tid >> 5;
    int lane = tid & 31;
    const u64* __restrict__ M = &g_mask[(size_t)b * MROWS * NW];

    // preload chunk 0 (all threads, uint4 vectorized)
    {
        const uint4* src = (const uint4*)M;
        uint4* dst = (uint4*)buf[0];
        for (int i = tid; i < 64 * NW / 2; i += 512) dst[i] = src[i];
    }
    __syncthreads();

    u64 remv = 0ull;                       // warp0: lane t owns removal word t
    for (int c = 0; c < NCH; c++) {
        if (warp == 0) {
            const u64* dp = buf[c & 1];
            u64 cur = __shfl_sync(FULL, remv, c);
            unsigned keptlo = 0, kepthi = 0;
            if (lane == 0) {
                unsigned clo = (unsigned)cur, chi = (unsigned)(cur >> 32);
                // rows 0..31: batches of 16, loads pipelined off the chain
                #pragma unroll
                for (int batch = 0; batch < 2; batch++) {
                    u64 d[16];
                    #pragma unroll
                    for (int r = 0; r < 16; r++)
                        d[r] = dp[(batch * 16 + r) * NW + c];
                    #pragma unroll
                    for (int r = 0; r < 16; r++) {
                        unsigned sel = ((clo >> (batch * 16 + r)) & 1u) - 1u;  // kept -> ~0
                        clo |= (unsigned)d[r] & sel;
                        chi |= (unsigned)(d[r] >> 32) & sel;
                    }
                }
                // rows 32..63: only high words matter (low half of mask is 0)
                const unsigned* dph = (const unsigned*)dp;
                #pragma unroll
                for (int batch = 0; batch < 2; batch++) {
                    unsigned dh[16];
                    #pragma unroll
                    for (int r = 0; r < 16; r++)
                        dh[r] = dph[2 * ((32 + batch * 16 + r) * NW + c) + 1];
                    #pragma unroll
                    for (int r = 0; r < 16; r++) {
                        unsigned sel = ((chi >> (batch * 16 + r)) & 1u) - 1u;
                        chi |= dh[r] & sel;
                    }
                }
                keptlo = ~clo; kepthi = ~chi;
            }
            unsigned klo = __shfl_sync(FULL, keptlo, 0);
            unsigned khi = __shfl_sync(FULL, kepthi, 0);
            if (lane == c) remv = ((u64)(~khi) << 32) | (u64)(~klo);
            // branchless OR of kept rows, 4 independent accumulators
            u64 a0 = 0, a1 = 0, a2 = 0, a3 = 0;
            #pragma unroll
            for (int r = 0; r < 32; r += 4) {
                a0 |= dp[(r    ) * NW + lane] & (u64)(-(long long)((klo >> (r    )) & 1u));
                a1 |= dp[(r + 1) * NW + lane] & (u64)(-(long long)((klo >> (r + 1)) & 1u));
                a2 |= dp[(r + 2) * NW + lane] & (u64)(-(long long)((klo >> (r + 2)) & 1u));
                a3 |= dp[(r + 3) * NW + lane] & (u64)(-(long long)((klo >> (r + 3)) & 1u));
            }
            #pragma unroll
            for (int r = 0; r < 32; r += 4) {
                a0 |= dp[(r + 32) * NW + lane] & (u64)(-(long long)((khi >> (r    )) & 1u));
                a1 |= dp[(r + 33) * NW + lane] & (u64)(-(long long)((khi >> (r + 1)) & 1u));
                a2 |= dp[(r + 34) * NW + lane] & (u64)(-(long long)((khi >> (r + 2)) & 1u));
                a3 |= dp[(r + 35) * NW + lane] & (u64)(-(long long)((khi >> (r + 3)) & 1u));
            }
            remv |= (a0 | a1) | (a2 | a3);
        } else if (c + 1 < NCH) {
            const uint4* src = (const uint4*)&M[(size_t)(c + 1) * 64 * NW];
            uint4* dst = (uint4*)buf[(c + 1) & 1];
            #pragma unroll 3
            for (int i = tid - 32; i < 64 * NW / 2; i += 480) dst[i] = src[i];
        }
        __syncthreads();
    }

    float* ob = &out[(size_t)b * POST * 5];
    for (int i = tid; i < POST * 5; i += 512) ob[i] = 0.0f;
    __syncthreads();

    if (warp == 0) {
        u64 keepw = ~remv;
        if (lane == NW - 1) keepw &= (1ull << (PRE - (NW - 1) * 64)) - 1ull;  // 16 bits
        int pc = __popcll(keepw);
        int inc = pc;
        #pragma unroll
        for (int o = 1; o < 32; o <<= 1) {
            int nn = __shfl_up_sync(FULL, inc, o);
            if (lane >= o) inc += nn;
        }
        int r = inc - pc;                  // exclusive prefix
        u64 w = keepw;
        while (w) {
            int bit = __ffsll((long long)w) - 1;
            w &= w - 1;
            if (r < POST) {
                int i = lane * 64 + bit;
                float4 bx = g_box[b * PRE + i];
                float sc = g_sc2[b * PRE + i];
                float* o = &ob[(size_t)r * 5];
                o[0] = bx.x; o[1] = bx.y; o[2] = bx.z; o[3] = bx.w; o[4] = sc;
            }
            r++;
        }
    }
}

// ---------------- launch ----------------
extern "C" void kernel_launch(void* const* d_in, const int* in_sizes, int n_in,
                              void* d_out, int out_size) {
    const float4* anchors = (const float4*)d_in[0];   // (A,4)
    const float4* deltas  = (const float4*)d_in[1];   // (B,A,4)
    const float*  scores  = (const float*)d_in[2];    // (B,A)
    float* out = (float*)d_out;                        // (B,POST,5)

    k_decode  <<<BATCH * 64, 512>>>(anchors, deltas, scores);
    k_sort    <<<BATCH, 1024>>>(anchors, deltas, scores);
    k_iou     <<<dim3(NW, (PRE + 63) / 64, BATCH), 64>>>();
    k_nms_out <<<BATCH, 512>>>(out);
}